// round 6
// baseline (speedup 1.0000x reference)
#include <cuda_runtime.h>
#include <cuda_fp16.h>
#include <math.h>
#include <stdint.h>

#define TOK 4096
#define HID 1024
#define FFN 4096
#define NE  8
#define NPART 64

#define BM 128
#define BN 256
#define BK 32                 // K elements per stage
#define WROW 20               // uint32 words per smem row (16 data + 4 pad = 40 halves)
#define STAGES 4
#define A_STG_W (BM * WROW)           // 2560 words / stage
#define B_STG_W (BN * WROW)           // 5120 words / stage
#define SMEM_WORDS (STAGES * (A_STG_W + B_STG_W))
#define SMEM_BYTES (SMEM_WORDS * 4)   // 122880

// ---------------- device scratch (static; no allocation) ----------------
__device__ float g_probsum_part[NE * NPART];
__device__ int   g_counts_part[NE * NPART];
__device__ int   g_offsets[NE + 1];
__device__ int   g_cursor[NE];
__device__ int   g_perm[TOK];
__device__ int   g_expert[TOK];
__device__ float g_gate[TOK];
// half-precision activation buffers (+BM padding rows for tile overreach)
__device__ __half g_xg[(size_t)(TOK + BM) * HID];
__device__ __half g_h[(size_t)(TOK + BM) * FFN];

// ---------------- init ----------------
__global__ void init_kernel() {
    int i = blockIdx.x * blockDim.x + threadIdx.x;
    if (i < NE * NPART) { g_probsum_part[i] = 0.f; g_counts_part[i] = 0; }
}

// ---------------- router ----------------
__global__ __launch_bounds__(256) void router_kernel(const float* __restrict__ x,
                                                     const float* __restrict__ rw) {
    int t = blockIdx.x;
    __shared__ float xs[HID];
    __shared__ float lg[NE];
    const float4* x4 = (const float4*)(x + (size_t)t * HID);
    ((float4*)xs)[threadIdx.x] = x4[threadIdx.x];
    __syncthreads();

    int w = threadIdx.x >> 5, lane = threadIdx.x & 31;
    const float* rwe = rw + w * HID;
    float s = 0.f;
    #pragma unroll 8
    for (int i = lane; i < HID; i += 32) s += xs[i] * rwe[i];
    #pragma unroll
    for (int o = 16; o; o >>= 1) s += __shfl_xor_sync(0xffffffffu, s, o);
    if (lane == 0) lg[w] = s;
    __syncthreads();

    if (threadIdx.x == 0) {
        float mx = lg[0]; int idx = 0;
        #pragma unroll
        for (int e = 1; e < NE; e++) if (lg[e] > mx) { mx = lg[e]; idx = e; }
        float p[NE]; float den = 0.f;
        #pragma unroll
        for (int e = 0; e < NE; e++) { p[e] = expf(lg[e] - mx); den += p[e]; }
        float inv = 1.f / den;
        int part = t & (NPART - 1);
        #pragma unroll
        for (int e = 0; e < NE; e++) atomicAdd(&g_probsum_part[e * NPART + part], p[e] * inv);
        g_gate[t] = p[idx] * inv;
        g_expert[t] = idx;
        atomicAdd(&g_counts_part[idx * NPART + part], 1);
    }
}

// ---------------- prefix ----------------
__global__ void prefix_kernel(float* __restrict__ out, int out_size) {
    __shared__ float ps[NE];
    __shared__ int   cs[NE];
    int tid = threadIdx.x;
    if (tid < NE) {
        float s = 0.f; int c = 0;
        for (int p = 0; p < NPART; p++) {
            s += g_probsum_part[tid * NPART + p];
            c += g_counts_part[tid * NPART + p];
        }
        ps[tid] = s; cs[tid] = c;
    }
    __syncthreads();
    if (tid == 0) {
        int run = 0; float aux = 0.f;
        for (int e = 0; e < NE; e++) {
            g_offsets[e] = run; g_cursor[e] = run;
            run += cs[e];
            aux += ps[e] * (float)cs[e];
        }
        g_offsets[NE] = run;
        aux *= 0.01f * (float)NE / ((float)TOK * (float)TOK);
        if (out_size > TOK * HID) out[TOK * HID] = aux;
    }
}

// ---------------- helpers ----------------
__device__ __forceinline__ uint32_t pk2(float a, float b) {
    __half2 h = __floats2half2_rn(a, b);
    return *(uint32_t*)&h;
}
__device__ __forceinline__ float gelu_exact(float v) {
    return 0.5f * v * (1.0f + erff(v * 0.70710678118654752f));
}
__device__ __forceinline__ void cp16(uint32_t saddr, const void* g) {
    asm volatile("cp.async.cg.shared.global [%0], [%1], 16;" :: "r"(saddr), "l"(g));
}
__device__ __forceinline__ void mma_f16(float c[4], const uint32_t a[4], const uint32_t b[2]) {
    asm volatile("mma.sync.aligned.m16n8k16.row.col.f32.f16.f16.f32 "
        "{%0,%1,%2,%3}, {%4,%5,%6,%7}, {%8,%9}, {%0,%1,%2,%3};"
        : "+f"(c[0]), "+f"(c[1]), "+f"(c[2]), "+f"(c[3])
        : "r"(a[0]), "r"(a[1]), "r"(a[2]), "r"(a[3]), "r"(b[0]), "r"(b[1]));
}

// ---------------- gather: tokens -> expert-contiguous, fp32 -> fp16 ----------------
__global__ __launch_bounds__(256) void gather_kernel(const float* __restrict__ x) {
    int t = blockIdx.x;
    __shared__ int slot_s;
    if (threadIdx.x == 0) {
        int e = g_expert[t];
        int slot = atomicAdd(&g_cursor[e], 1);
        g_perm[slot] = t;
        slot_s = slot;
    }
    __syncthreads();
    int slot = slot_s;
    float4 v = ((const float4*)(x + (size_t)t * HID))[threadIdx.x];
    uint2 o; o.x = pk2(v.x, v.y); o.y = pk2(v.z, v.w);
    ((uint2*)(g_xg + (size_t)slot * HID))[threadIdx.x] = o;
}

// ---------------- grouped fp16 tensor-core GEMM ----------------
// CTA tile 128x256, 8 warps in 2x4 grid of 64x64 warp tiles, 4-stage smem ring.
// A (fp16 activations) staged via cp.async; B (fp32 weights) LDG->cvt->STS.
template<int KDIM, bool IS_FC1>
__global__ __launch_bounds__(256, 1) void gemm_tc(const float* __restrict__ W,
                                                  const float* __restrict__ bias,
                                                  float* __restrict__ outp) {
    int e = blockIdx.z;
    int off = g_offsets[e];
    int ne  = g_offsets[e + 1] - off;
    int m0  = blockIdx.y * BM;
    if (m0 >= ne) return;
    int n0 = blockIdx.x * BN;

    const int NDIM = IS_FC1 ? FFN : HID;
    const __half* Ag = (IS_FC1 ? g_xg : g_h) + (size_t)(off + m0) * KDIM;
    const float*  Bg = W + (size_t)e * NDIM * KDIM + (size_t)n0 * KDIM;

    extern __shared__ uint32_t sm[];
    uint32_t* smB = sm + STAGES * A_STG_W;

    int tid = threadIdx.x;

    // ---- producer mapping ----
    // A: 128 rows x 32 halves/stage; thread t -> row t>>1, halves (t&1)*16..+15 (2 x cp.async 16B)
    int arow = tid >> 1, ahalf = (tid & 1) * 16;
    uint32_t aDst = (uint32_t)__cvta_generic_to_shared(&sm[arow * WROW + (tid & 1) * 8]);
    const __half* aSrc = Ag + (size_t)arow * KDIM + ahalf;
    // B: 256 rows x 32 floats/stage; thread t -> row t (8 LDG.128 -> cvt -> 4 STS.128)
    const float* bSrc = Bg + (size_t)tid * KDIM;
    uint4* bDst = (uint4*)&smB[tid * WROW];

    // ---- consumer mapping ----
    int wid = tid >> 5, lane = tid & 31;
    int wm = wid & 1;          // m offset wm*64
    int wn = wid >> 1;         // n offset wn*64
    int g  = lane >> 2;
    int t4 = lane & 3;

    float acc[4][8][4] = {};

    // ---- prologue: stages 0,1 ----
    #pragma unroll
    for (int s = 0; s < 2; s++) {
        cp16(aDst + s * A_STG_W * 4, aSrc + s * BK);
        cp16(aDst + s * A_STG_W * 4 + 16, aSrc + s * BK + 8);
        float4 q[8];
        #pragma unroll
        for (int i = 0; i < 8; i++) q[i] = *(const float4*)(bSrc + s * BK + i * 4);
        uint4* d = (uint4*)((char*)bDst + s * B_STG_W * 4);
        #pragma unroll
        for (int i = 0; i < 4; i++) {
            uint4 u;
            u.x = pk2(q[2*i].x, q[2*i].y);   u.y = pk2(q[2*i].z, q[2*i].w);
            u.z = pk2(q[2*i+1].x, q[2*i+1].y); u.w = pk2(q[2*i+1].z, q[2*i+1].w);
            d[i] = u;
        }
        asm volatile("cp.async.commit_group;" ::: "memory");
    }
    asm volatile("cp.async.wait_group 1;" ::: "memory");
    __syncthreads();

    const int KT = KDIM / BK;
    for (int kt = 0; kt < KT; kt++) {
        int s = kt & (STAGES - 1);
        int ns = (kt + 2) & (STAGES - 1);
        bool more = (kt + 2 < KT);

        float4 q[8];
        if (more) {
            int k0 = (kt + 2) * BK;
            cp16(aDst + ns * A_STG_W * 4, aSrc + k0);
            cp16(aDst + ns * A_STG_W * 4 + 16, aSrc + k0 + 8);
            #pragma unroll
            for (int i = 0; i < 8; i++) q[i] = *(const float4*)(bSrc + k0 + i * 4);
        }
        asm volatile("cp.async.commit_group;" ::: "memory");

        const uint32_t* As = sm + s * A_STG_W;
        const uint32_t* Bs = smB + s * B_STG_W;
        #pragma unroll
        for (int ks = 0; ks < 2; ks++) {       // two k16 slices per stage
            int kb = ks * 8;
            uint32_t a[4][4];
            #pragma unroll
            for (int i = 0; i < 4; i++) {
                int rm = wm * 64 + i * 16 + g;
                a[i][0] = As[rm * WROW + kb + t4];
                a[i][1] = As[(rm + 8) * WROW + kb + t4];
                a[i][2] = As[rm * WROW + kb + t4 + 4];
                a[i][3] = As[(rm + 8) * WROW + kb + t4 + 4];
            }
            uint32_t b[8][2];
            #pragma unroll
            for (int j = 0; j < 8; j++) {
                int rn = wn * 64 + j * 8 + g;
                b[j][0] = Bs[rn * WROW + kb + t4];
                b[j][1] = Bs[rn * WROW + kb + t4 + 4];
            }
            #pragma unroll
            for (int i = 0; i < 4; i++)
                #pragma unroll
                for (int j = 0; j < 8; j++)
                    mma_f16(acc[i][j], a[i], b[j]);
        }

        if (more) {
            uint4* d = (uint4*)((char*)bDst + ns * B_STG_W * 4);
            #pragma unroll
            for (int i = 0; i < 4; i++) {
                uint4 u;
                u.x = pk2(q[2*i].x, q[2*i].y);     u.y = pk2(q[2*i].z, q[2*i].w);
                u.z = pk2(q[2*i+1].x, q[2*i+1].y); u.w = pk2(q[2*i+1].z, q[2*i+1].w);
                d[i] = u;
            }
        }
        asm volatile("cp.async.wait_group 1;" ::: "memory");
        __syncthreads();
    }

    // ---------------- epilogue ----------------
    #pragma unroll
    for (int i = 0; i < 4; i++) {
        int rml = wm * 64 + i * 16 + g;
        #pragma unroll
        for (int j = 0; j < 8; j++) {
            int col = n0 + wn * 64 + j * 8 + 2 * t4;
            if (IS_FC1) {
                float b0v = bias[(size_t)e * FFN + col];
                float b1v = bias[(size_t)e * FFN + col + 1];
                int m_ = m0 + rml;
                if (m_ < ne) {
                    *(uint32_t*)&g_h[(size_t)(off + m_) * FFN + col] =
                        pk2(gelu_exact(acc[i][j][0] + b0v), gelu_exact(acc[i][j][1] + b1v));
                }
                if (m_ + 8 < ne) {
                    *(uint32_t*)&g_h[(size_t)(off + m_ + 8) * FFN + col] =
                        pk2(gelu_exact(acc[i][j][2] + b0v), gelu_exact(acc[i][j][3] + b1v));
                }
            } else {
                float b0v = bias[(size_t)e * HID + col];
                float b1v = bias[(size_t)e * HID + col + 1];
                int m_ = m0 + rml;
                if (m_ < ne) {
                    int tok = g_perm[off + m_];
                    float gt = g_gate[tok];
                    float2 o;
                    o.x = (acc[i][j][0] + b0v) * gt;
                    o.y = (acc[i][j][1] + b1v) * gt;
                    *(float2*)&outp[(size_t)tok * HID + col] = o;
                }
                if (m_ + 8 < ne) {
                    int tok = g_perm[off + m_ + 8];
                    float gt = g_gate[tok];
                    float2 o;
                    o.x = (acc[i][j][2] + b0v) * gt;
                    o.y = (acc[i][j][3] + b1v) * gt;
                    *(float2*)&outp[(size_t)tok * HID + col] = o;
                }
            }
        }
    }
}

// ---------------- launch ----------------
extern "C" void kernel_launch(void* const* d_in, const int* in_sizes, int n_in,
                              void* d_out, int out_size) {
    const float* x        = (const float*)d_in[0];
    const float* router_w = (const float*)d_in[1];
    const float* fc1_w    = (const float*)d_in[2];
    const float* fc1_b    = (const float*)d_in[3];
    const float* fc2_w    = (const float*)d_in[4];
    const float* fc2_b    = (const float*)d_in[5];
    float* out = (float*)d_out;

    cudaFuncSetAttribute(gemm_tc<HID, true>,  cudaFuncAttributeMaxDynamicSharedMemorySize, SMEM_BYTES);
    cudaFuncSetAttribute(gemm_tc<FFN, false>, cudaFuncAttributeMaxDynamicSharedMemorySize, SMEM_BYTES);

    init_kernel<<<(NE * NPART + 255) / 256, 256>>>();
    router_kernel<<<TOK, 256>>>(x, router_w);
    prefix_kernel<<<1, 256>>>(out, out_size);
    gather_kernel<<<TOK, 256>>>(x);

    dim3 g1(FFN / BN, TOK / BM, NE);   // 16 x 32 x 8, early-exit tiles
    gemm_tc<HID, true><<<g1, 256, SMEM_BYTES>>>(fc1_w, fc1_b, nullptr);

    dim3 g2(HID / BN, TOK / BM, NE);   // 4 x 32 x 8
    gemm_tc<FFN, false><<<g2, 256, SMEM_BYTES>>>(fc2_w, fc2_b, out);
}

// round 7
// speedup vs baseline: 1.0872x; 1.0872x over previous
#include <cuda_runtime.h>
#include <math.h>
#include <stdint.h>

#define TOK 4096
#define HID 1024
#define FFN 4096
#define NE  8
#define NPART 64

#define BM 128
#define BN 128
#define BK 32
#define SROW 36                         // words per smem row (32 data + 4 pad)
#define STAGES 3
#define STG_W ((BM + BN) * SROW)        // 9216 words per stage
#define SMEM_BYTES (STAGES * STG_W * 4) // 110592

// ---------------- device scratch (static; no allocation) ----------------
__device__ float g_probsum_part[NE * NPART];
__device__ int   g_counts_part[NE * NPART];
__device__ int   g_offsets[NE + 1];
__device__ int   g_cursor[NE];
__device__ int   g_perm[TOK];
__device__ int   g_expert[TOK];
__device__ float g_gate[TOK];
// +BM zero rows of padding so GEMM tiles can read past segment ends safely
__device__ float g_xg[(size_t)(TOK + BM) * HID];
__device__ float g_h[(size_t)(TOK + BM) * FFN];

// ---------------- router ----------------
__global__ __launch_bounds__(256) void router_kernel(const float* __restrict__ x,
                                                     const float* __restrict__ rw) {
    int t = blockIdx.x;
    __shared__ float xs[HID];
    __shared__ float lg[NE];
    const float4* x4 = (const float4*)(x + (size_t)t * HID);
    ((float4*)xs)[threadIdx.x] = x4[threadIdx.x];
    __syncthreads();

    int w = threadIdx.x >> 5, lane = threadIdx.x & 31;
    const float* rwe = rw + w * HID;
    float s = 0.f;
    #pragma unroll 8
    for (int i = lane; i < HID; i += 32) s += xs[i] * rwe[i];
    #pragma unroll
    for (int o = 16; o; o >>= 1) s += __shfl_xor_sync(0xffffffffu, s, o);
    if (lane == 0) lg[w] = s;
    __syncthreads();

    if (threadIdx.x == 0) {
        float mx = lg[0]; int idx = 0;
        #pragma unroll
        for (int e = 1; e < NE; e++) if (lg[e] > mx) { mx = lg[e]; idx = e; }
        float p[NE]; float den = 0.f;
        #pragma unroll
        for (int e = 0; e < NE; e++) { p[e] = expf(lg[e] - mx); den += p[e]; }
        float inv = 1.f / den;
        int part = t & (NPART - 1);
        #pragma unroll
        for (int e = 0; e < NE; e++) atomicAdd(&g_probsum_part[e * NPART + part], p[e] * inv);
        g_gate[t] = p[idx] * inv;
        g_expert[t] = idx;
        atomicAdd(&g_counts_part[idx * NPART + part], 1);
    }
}

// ---------------- prefix (also re-zeroes accumulators for the next replay) ----------------
__global__ __launch_bounds__(256) void prefix_kernel(float* __restrict__ out, int out_size) {
    __shared__ float ps[NE];
    __shared__ int   cs[NE];
    int tid = threadIdx.x;
    if (tid < NE) {
        float s = 0.f; int c = 0;
        for (int p = 0; p < NPART; p++) {
            s += g_probsum_part[tid * NPART + p];
            c += g_counts_part[tid * NPART + p];
        }
        ps[tid] = s; cs[tid] = c;
    }
    __syncthreads();
    // re-zero partitioned accumulators (keeps device state replay-invariant)
    for (int i = tid; i < NE * NPART; i += 256) { g_probsum_part[i] = 0.f; g_counts_part[i] = 0; }
    if (tid == 0) {
        int run = 0; float aux = 0.f;
        for (int e = 0; e < NE; e++) {
            g_offsets[e] = run; g_cursor[e] = run;
            run += cs[e];
            aux += ps[e] * (float)cs[e];
        }
        g_offsets[NE] = run;
        aux *= 0.01f * (float)NE / ((float)TOK * (float)TOK);
        if (out_size > TOK * HID) out[TOK * HID] = aux;
    }
}

// ---------------- gather ----------------
__global__ __launch_bounds__(256) void gather_kernel(const float* __restrict__ x) {
    int t = blockIdx.x;
    __shared__ int slot_s;
    if (threadIdx.x == 0) {
        int e = g_expert[t];
        int slot = atomicAdd(&g_cursor[e], 1);
        g_perm[slot] = t;
        slot_s = slot;
    }
    __syncthreads();
    int slot = slot_s;
    const float4* src = (const float4*)(x + (size_t)t * HID);
    float4* dst = (float4*)(g_xg + (size_t)slot * HID);
    dst[threadIdx.x] = src[threadIdx.x];
}

// ---------------- helpers ----------------
__device__ __forceinline__ float gelu_exact(float v) {
    return 0.5f * v * (1.0f + erff(v * 0.70710678118654752f));
}
__device__ __forceinline__ uint32_t cvt_tf32(float f) {
    uint32_t u; asm("cvt.rna.tf32.f32 %0, %1;" : "=r"(u) : "f"(f)); return u;
}
__device__ __forceinline__ void cp16(uint32_t saddr, const void* g) {
    asm volatile("cp.async.cg.shared.global [%0], [%1], 16;" :: "r"(saddr), "l"(g));
}
__device__ __forceinline__ void mma_tf32(float c[4], const uint32_t a[4], const uint32_t b[2]) {
    asm volatile("mma.sync.aligned.m16n8k8.row.col.f32.tf32.tf32.f32 "
        "{%0,%1,%2,%3}, {%4,%5,%6,%7}, {%8,%9}, {%0,%1,%2,%3};"
        : "+f"(c[0]), "+f"(c[1]), "+f"(c[2]), "+f"(c[3])
        : "r"(a[0]), "r"(a[1]), "r"(a[2]), "r"(a[3]), "r"(b[0]), "r"(b[1]));
}

// ---------------- grouped tensor-core GEMM ----------------
// CTA tile 128x128, 128 threads = 4 warps in 2x2 grid of 64x64 warp tiles.
// 3-stage BK=32 smem ring, 2 CTAs/SM.
template<int KDIM, bool IS_FC1>
__global__ __launch_bounds__(128, 2) void gemm_tc(const float* __restrict__ W,
                                                  const float* __restrict__ bias,
                                                  float* __restrict__ outp) {
    int e = blockIdx.z;
    int off = g_offsets[e];
    int ne  = g_offsets[e + 1] - off;
    int m0  = blockIdx.y * BM;
    if (m0 >= ne) return;
    int n0 = blockIdx.x * BN;

    const int NDIM = IS_FC1 ? FFN : HID;
    const float* A = (IS_FC1 ? g_xg : g_h) + (size_t)(off + m0) * KDIM;
    const float* B = W + (size_t)e * NDIM * KDIM + (size_t)n0 * KDIM;

    extern __shared__ float sm[];   // [STAGES][256 rows][SROW]; rows 0-127 = A, 128-255 = B

    int tid = threadIdx.x;

    // loader: 2048 16B-chunks per stage (A rows 0-127, B rows 128-255), 16 per thread
    int rowc[16], kqc[16];
    #pragma unroll
    for (int t = 0; t < 16; t++) { int c = tid + t * 128; rowc[t] = c >> 3; kqc[t] = (c & 7) * 4; }

    uint32_t sDst[16];
    #pragma unroll
    for (int t = 0; t < 16; t++)
        sDst[t] = (uint32_t)__cvta_generic_to_shared(&sm[rowc[t] * SROW + kqc[t]]);

    const float* gSrc[16];
    #pragma unroll
    for (int t = 0; t < 16; t++) {
        int r = rowc[t];
        gSrc[t] = (r < BM) ? (A + (size_t)r * KDIM + kqc[t])
                           : (B + (size_t)(r - BM) * KDIM + kqc[t]);
    }

    // ---- prologue: stages 0,1 ----
    #pragma unroll
    for (int s = 0; s < 2; s++) {
        #pragma unroll
        for (int t = 0; t < 16; t++) cp16(sDst[t] + s * STG_W * 4, gSrc[t] + s * BK);
        asm volatile("cp.async.commit_group;" ::: "memory");
    }

    int wid = tid >> 5, lane = tid & 31;
    int wm = wid & 1;        // m offset wm*64
    int wn = wid >> 1;       // n offset wn*64
    int g  = lane >> 2;
    int t4 = lane & 3;

    float acc[4][8][4] = {};

    const int KT = KDIM / BK;
    int s = 0;
    for (int kt = 0; kt < KT; kt++) {
        asm volatile("cp.async.wait_group 1;" ::: "memory");
        __syncthreads();

        int nk = kt + 2;
        if (nk < KT) {
            int ns = s + 2; if (ns >= STAGES) ns -= STAGES;
            int ko = nk * BK;
            #pragma unroll
            for (int t = 0; t < 16; t++) cp16(sDst[t] + ns * STG_W * 4, gSrc[t] + ko);
        }
        asm volatile("cp.async.commit_group;" ::: "memory");

        const float* As = sm + s * STG_W;
        const float* Bs = As + BM * SROW;
        #pragma unroll
        for (int ks = 0; ks < BK / 8; ks++) {
            int kb = ks * 8;
            uint32_t a[4][4];
            #pragma unroll
            for (int i = 0; i < 4; i++) {
                int rm = wm * 64 + i * 16 + g;
                a[i][0] = cvt_tf32(As[rm * SROW + kb + t4]);
                a[i][1] = cvt_tf32(As[(rm + 8) * SROW + kb + t4]);
                a[i][2] = cvt_tf32(As[rm * SROW + kb + t4 + 4]);
                a[i][3] = cvt_tf32(As[(rm + 8) * SROW + kb + t4 + 4]);
            }
            uint32_t b[8][2];
            #pragma unroll
            for (int j = 0; j < 8; j++) {
                int rn = wn * 64 + j * 8 + g;
                b[j][0] = cvt_tf32(Bs[rn * SROW + kb + t4]);
                b[j][1] = cvt_tf32(Bs[rn * SROW + kb + t4 + 4]);
            }
            #pragma unroll
            for (int i = 0; i < 4; i++)
                #pragma unroll
                for (int j = 0; j < 8; j++)
                    mma_tf32(acc[i][j], a[i], b[j]);
        }
        s++; if (s == STAGES) s = 0;
    }

    // ---------------- epilogue ----------------
    #pragma unroll
    for (int i = 0; i < 4; i++) {
        int rml = wm * 64 + i * 16 + g;
        #pragma unroll
        for (int j = 0; j < 8; j++) {
            int col = n0 + wn * 64 + j * 8 + 2 * t4;
            if (IS_FC1) {
                float b0v = bias[(size_t)e * FFN + col];
                float b1v = bias[(size_t)e * FFN + col + 1];
                int m_ = m0 + rml;
                if (m_ < ne) {
                    float2 o;
                    o.x = gelu_exact(acc[i][j][0] + b0v);
                    o.y = gelu_exact(acc[i][j][1] + b1v);
                    *(float2*)&g_h[(size_t)(off + m_) * FFN + col] = o;
                }
                if (m_ + 8 < ne) {
                    float2 o;
                    o.x = gelu_exact(acc[i][j][2] + b0v);
                    o.y = gelu_exact(acc[i][j][3] + b1v);
                    *(float2*)&g_h[(size_t)(off + m_ + 8) * FFN + col] = o;
                }
            } else {
                float b0v = bias[(size_t)e * HID + col];
                float b1v = bias[(size_t)e * HID + col + 1];
                int m_ = m0 + rml;
                if (m_ < ne) {
                    int tok = g_perm[off + m_];
                    float gt = g_gate[tok];
                    float2 o;
                    o.x = (acc[i][j][0] + b0v) * gt;
                    o.y = (acc[i][j][1] + b1v) * gt;
                    *(float2*)&outp[(size_t)tok * HID + col] = o;
                }
                if (m_ + 8 < ne) {
                    int tok = g_perm[off + m_ + 8];
                    float gt = g_gate[tok];
                    float2 o;
                    o.x = (acc[i][j][2] + b0v) * gt;
                    o.y = (acc[i][j][3] + b1v) * gt;
                    *(float2*)&outp[(size_t)tok * HID + col] = o;
                }
            }
        }
    }
}

// ---------------- launch ----------------
extern "C" void kernel_launch(void* const* d_in, const int* in_sizes, int n_in,
                              void* d_out, int out_size) {
    const float* x        = (const float*)d_in[0];
    const float* router_w = (const float*)d_in[1];
    const float* fc1_w    = (const float*)d_in[2];
    const float* fc1_b    = (const float*)d_in[3];
    const float* fc2_w    = (const float*)d_in[4];
    const float* fc2_b    = (const float*)d_in[5];
    float* out = (float*)d_out;

    cudaFuncSetAttribute(gemm_tc<HID, true>,  cudaFuncAttributeMaxDynamicSharedMemorySize, SMEM_BYTES);
    cudaFuncSetAttribute(gemm_tc<FFN, false>, cudaFuncAttributeMaxDynamicSharedMemorySize, SMEM_BYTES);

    router_kernel<<<TOK, 256>>>(x, router_w);
    prefix_kernel<<<1, 256>>>(out, out_size);
    gather_kernel<<<TOK, 256>>>(x);

    dim3 g1(FFN / BN, TOK / BM, NE);   // 32 x 32 x 8, early-exit tiles
    gemm_tc<HID, true><<<g1, 128, SMEM_BYTES>>>(fc1_w, fc1_b, nullptr);

    dim3 g2(HID / BN, TOK / BM, NE);   // 8 x 32 x 8
    gemm_tc<FFN, false><<<g2, 128, SMEM_BYTES>>>(fc2_w, fc2_b, out);
}